// round 15
// baseline (speedup 1.0000x reference)
#include <cuda_runtime.h>
#include <cuda_fp16.h>
#include <cstdint>

#define B_  8
#define T_  200
#define U_  50
#define DE  512
#define DP  640
#define DJ  640
#define V_  1024

#define MT     64                  // joint M rows per CTA (8 t x 8 u)
#define NTILE  256
#define NPASS  (V_ / NTILE)        // 4
#define KSTEPS (DJ / 16)           // 40

#define SA   648
#define SAW  324

#define AS_BYTES   (MT * SA * 2)               // 82944
#define ENC_OFF    AS_BYTES
#define PRED_OFF   (ENC_OFF + 8 * 64 * 4)
#define JOINT_SMEM (PRED_OFF + 8 * 64 * 4)     // 87040

// Frag buffer layout (uint4 units)
#define ENCF_OFF    0                          // 100 m16 x 32 ks x 32
#define PREDF_OFF   102400                     // 25 m16 x 40 ks x 32
#define WENCF_OFF   134400                     // 40 n16 x 32 ks x 32
#define WPREDF_OFF  175360                     // 40 n16 x 40 ks x 32
#define WOUTF_OFF   226560                     // 64 n16 x 40 ks x 32
#define FRAG_TOTAL  308480

// Scratch
__device__ float g_enc [B_ * T_ * DJ];
__device__ float g_pred[B_ * U_ * DJ];
__device__ __align__(16) uint4 g_frag[FRAG_TOTAL];   // 4.9 MB

// ---------------------------------------------------------------------------
__device__ __forceinline__ uint32_t smem_u32(const void* p) {
    return (uint32_t)__cvta_generic_to_shared(p);
}
__device__ __forceinline__ void ldsm_x4(uint32_t& r0, uint32_t& r1, uint32_t& r2,
                                        uint32_t& r3, uint32_t a) {
    asm volatile("ldmatrix.sync.aligned.m8n8.x4.shared.b16 {%0,%1,%2,%3}, [%4];\n"
                 : "=r"(r0), "=r"(r1), "=r"(r2), "=r"(r3) : "r"(a));
}
__device__ __forceinline__ float tanh_fast(float x) {
    float y;
    asm("tanh.approx.f32 %0, %1;" : "=f"(y) : "f"(x));
    return y;
}
__device__ __forceinline__ uint32_t packh2(float a, float b) {
    half2 h = __floats2half2_rn(a, b);
    return *(uint32_t*)&h;
}
#define MMA16816(acc, a0, a1, a2, a3, bf0, bf1)                               \
    asm volatile(                                                             \
        "mma.sync.aligned.m16n8k16.row.col.f32.f16.f16.f32 "                  \
        "{%0,%1,%2,%3}, {%4,%5,%6,%7}, {%8,%9}, {%0,%1,%2,%3};\n"             \
        : "+f"((acc)[0]), "+f"((acc)[1]), "+f"((acc)[2]), "+f"((acc)[3])      \
        : "r"(a0), "r"(a1), "r"(a2), "r"(a3), "r"(bf0), "r"(bf1))

// ---------------------------------------------------------------------------
// Flat convert kernel: fp32 -> fp16 frag shuffles for all 5 tensors.
// A-layout frag (activations): {x:[g][k], y:[g+8][k], z:[g][k+8], w:[g+8][k+8]}
// B-layout frag (weights):     {x:[g][k], y:[g][k+8], z:[g+8][k], w:[g+8][k+8]}
// index within region = (row16 * KS + ks) * 32 + lane
// ---------------------------------------------------------------------------
__global__ __launch_bounds__(256)
void convert_kernel(const float* __restrict__ enc, const float* __restrict__ pred,
                    const float* __restrict__ Wenc, const float* __restrict__ Wpred,
                    const float* __restrict__ Wout) {
    int gid = blockIdx.x * 256 + threadIdx.x;
    if (gid >= FRAG_TOTAL) return;
    int lane = gid & 31;
    int g = lane >> 2, tg = lane & 3;

    const float* src;
    int r16, ks, D;
    bool aL;
    if (gid < PREDF_OFF) {
        int t = gid >> 5;                src = enc;   D = DE;  aL = true;
        r16 = t / 32; ks = t % 32;
    } else if (gid < WENCF_OFF) {
        int t = (gid - PREDF_OFF) >> 5;  src = pred;  D = DP;  aL = true;
        r16 = t / 40; ks = t % 40;
    } else if (gid < WPREDF_OFF) {
        int t = (gid - WENCF_OFF) >> 5;  src = Wenc;  D = DE;  aL = false;
        r16 = t / 32; ks = t % 32;
    } else if (gid < WOUTF_OFF) {
        int t = (gid - WPREDF_OFF) >> 5; src = Wpred; D = DP;  aL = false;
        r16 = t / 40; ks = t % 40;
    } else {
        int t = (gid - WOUTF_OFF) >> 5;  src = Wout;  D = DJ;  aL = false;
        r16 = t / 40; ks = t % 40;
    }

    const float* p00 = src + (size_t)(r16 * 16 + g) * D + ks * 16 + tg * 2;
    const float* p10 = p00 + 8 * D;
    float2 v00 = *(const float2*)p00;
    float2 v01 = *(const float2*)(p00 + 8);
    float2 v10 = *(const float2*)p10;
    float2 v11 = *(const float2*)(p10 + 8);
    uint4 o;
    o.x = packh2(v00.x, v00.y);
    o.w = packh2(v11.x, v11.y);
    if (aL) { o.y = packh2(v10.x, v10.y); o.z = packh2(v01.x, v01.y); }
    else    { o.y = packh2(v01.x, v01.y); o.z = packh2(v10.x, v10.y); }
    g_frag[gid] = o;
}

// ---------------------------------------------------------------------------
// Projection GEMMs on tensor cores. CTA = one m16 row-block x full J=640.
// blocks 0..99: enc (KS=32), blocks 100..124: pred (KS=40).
// 8 warps, each covers 5 n16 blocks (80 cols). No smem, no barriers.
// ---------------------------------------------------------------------------
__global__ __launch_bounds__(256)
void proj_mma_kernel(const float* __restrict__ benc, const float* __restrict__ bpred) {
    int bx = blockIdx.x;
    bool isP = bx >= 100;
    int m16 = isP ? bx - 100 : bx;
    int KS = isP ? 40 : 32;
    const uint4* AF = g_frag + (isP ? PREDF_OFF : ENCF_OFF);
    const uint4* BF = g_frag + (isP ? WPREDF_OFF : WENCF_OFF);
    const float* bias = isP ? bpred : benc;
    float* C = isP ? g_pred : g_enc;

    int wid = threadIdx.x >> 5, lane = threadIdx.x & 31;
    int g = lane >> 2, tg = lane & 3;

    float acc[5][2][4];
    #pragma unroll
    for (int p = 0; p < 5; p++)
        #pragma unroll
        for (int nb = 0; nb < 2; nb++)
            #pragma unroll
            for (int c = 0; c < 4; c++) acc[p][nb][c] = 0.f;

    const uint4* ap = AF + (size_t)m16 * KS * 32 + lane;
    const uint4* bp = BF + (size_t)(wid * 5) * KS * 32 + lane;

    for (int ks = 0; ks < KS; ks++) {
        uint4 a = ap[ks * 32];
        #pragma unroll
        for (int p = 0; p < 5; p++) {
            uint4 bq = bp[((size_t)p * KS + ks) * 32];
            MMA16816(acc[p][0], a.x, a.y, a.z, a.w, bq.x, bq.y);
            MMA16816(acc[p][1], a.x, a.y, a.z, a.w, bq.z, bq.w);
        }
    }

    int r0 = m16 * 16 + g;
    #pragma unroll
    for (int p = 0; p < 5; p++) {
        #pragma unroll
        for (int nb = 0; nb < 2; nb++) {
            int n = (wid * 5 + p) * 16 + nb * 8 + tg * 2;
            float bo0 = bias[n], bo1 = bias[n + 1];
            *(float2*)(C + (size_t)r0 * DJ + n) =
                make_float2(acc[p][nb][0] + bo0, acc[p][nb][1] + bo1);
            *(float2*)(C + (size_t)(r0 + 8) * DJ + n) =
                make_float2(acc[p][nb][2] + bo0, acc[p][nb][3] + bo1);
        }
    }
}

// ---------------------------------------------------------------------------
// Joint kernel (unchanged 400us config): CTA = 64 M-rows x V=1024,
// 4 passes of N=256, 8 warps 2m x 4n, 2 CTAs/SM, no phase-2 barriers.
// ---------------------------------------------------------------------------
extern __shared__ __align__(128) char dynsmem[];

__global__ __launch_bounds__(256, 2)
void joint_kernel(const float* __restrict__ bout, float* __restrict__ out) {
    half*  As    = (half*)dynsmem;
    float* encs  = (float*)(dynsmem + ENC_OFF);
    float* preds = (float*)(dynsmem + PRED_OFF);

    int tid = threadIdx.x;
    int wid = tid >> 5, lane = tid & 31;
    int g = lane >> 2, tg = lane & 3;
    int warp_m = wid >> 2, warp_n = wid & 3;

    int bx = blockIdx.x;               // 1400 CTAs
    int b = bx / 175, r = bx % 175;
    int tt = r % 25, ut = r / 25;
    int t0 = tt * 8, u0 = ut * 8;

    uint32_t as_u = smem_u32(As);

    const float* encp  = g_enc  + ((size_t)b * T_ + t0) * DJ;
    const float* predp = g_pred + ((size_t)b * U_ + u0) * DJ;
    for (int kc = 0; kc < DJ; kc += 64) {
        {
            int rw = tid >> 5, kp = tid & 31;
            *(float2*)(encs + rw * 64 + kp * 2) =
                *(const float2*)(encp + (size_t)rw * DJ + kc + kp * 2);
            int u = u0 + rw;
            float2 pv = make_float2(0.f, 0.f);
            if (u < U_) pv = *(const float2*)(predp + (size_t)rw * DJ + kc + kp * 2);
            *(float2*)(preds + rw * 64 + kp * 2) = pv;
        }
        __syncthreads();
        #pragma unroll
        for (int i = 0; i < 8; i++) {
            int idx = tid + i * 256;
            int row = idx >> 5, kp = idx & 31;
            float2 e = *(const float2*)(encs + ((row >> 3) << 6) + kp * 2);
            float2 p = *(const float2*)(preds + ((row & 7) << 6) + kp * 2);
            half2 h = __floats2half2_rn(tanh_fast(e.x + p.x), tanh_fast(e.y + p.y));
            *(half2*)(As + row * SA + kc + kp * 2) = h;
        }
        __syncthreads();
    }

    int j = lane >> 3;
    int a_row = warp_m * 32 + (lane & 7) + (j & 1) * 8;
    int a_col = (j >> 1) * 4;

    const uint4* wsh = g_frag + WOUTF_OFF;

    for (int np = 0; np < NPASS; np++) {
        float acc[2][8][4];
        #pragma unroll
        for (int mt = 0; mt < 2; mt++)
            #pragma unroll
            for (int nt = 0; nt < 8; nt++)
                #pragma unroll
                for (int c = 0; c < 4; c++) acc[mt][nt][c] = 0.f;

        int n16b = np * (NTILE / 16) + warp_n * 4;
        const uint4* wp0 = wsh + ((size_t)(n16b + 0) * KSTEPS) * 32 + lane;
        const uint4* wp1 = wsh + ((size_t)(n16b + 1) * KSTEPS) * 32 + lane;
        const uint4* wp2 = wsh + ((size_t)(n16b + 2) * KSTEPS) * 32 + lane;
        const uint4* wp3 = wsh + ((size_t)(n16b + 3) * KSTEPS) * 32 + lane;

        for (int ks = 0; ks < KSTEPS; ks++) {
            uint4 bq[4];
            bq[0] = wp0[ks * 32];
            bq[1] = wp1[ks * 32];
            bq[2] = wp2[ks * 32];
            bq[3] = wp3[ks * 32];

            uint32_t a[2][4];
            #pragma unroll
            for (int mt = 0; mt < 2; mt++)
                ldsm_x4(a[mt][0], a[mt][1], a[mt][2], a[mt][3],
                        as_u + (uint32_t)((a_row + mt * 16) * SAW
                                          + ks * 8 + a_col) * 4);
            #pragma unroll
            for (int mt = 0; mt < 2; mt++) {
                #pragma unroll
                for (int nt = 0; nt < 8; nt++) {
                    uint32_t bf0 = (nt & 1) ? bq[nt >> 1].z : bq[nt >> 1].x;
                    uint32_t bf1 = (nt & 1) ? bq[nt >> 1].w : bq[nt >> 1].y;
                    MMA16816(acc[mt][nt], a[mt][0], a[mt][1], a[mt][2], a[mt][3],
                             bf0, bf1);
                }
            }
        }

        int n0 = np * NTILE;
        #pragma unroll
        for (int nt = 0; nt < 8; nt++) {
            int n = n0 + warp_n * 64 + nt * 8 + tg * 2;
            float bo0 = __ldg(bout + n);
            float bo1 = __ldg(bout + n + 1);
            #pragma unroll
            for (int mt = 0; mt < 2; mt++) {
                #pragma unroll
                for (int h = 0; h < 2; h++) {
                    int row = warp_m * 32 + mt * 16 + g + h * 8;
                    int t = t0 + (row >> 3), u = u0 + (row & 7);
                    if (u < U_) {
                        size_t base = ((((size_t)b * T_ + t) * U_ + u) * V_) + n;
                        float2 v = make_float2(acc[mt][nt][h * 2] + bo0,
                                               acc[mt][nt][h * 2 + 1] + bo1);
                        *(float2*)(out + base) = v;
                    }
                }
            }
        }
    }
}

// ---------------------------------------------------------------------------
extern "C" void kernel_launch(void* const* d_in, const int* in_sizes, int n_in,
                              void* d_out, int out_size) {
    const float* encoder_out   = (const float*)d_in[0];
    const float* predictor_out = (const float*)d_in[1];
    const float* W_enc  = (const float*)d_in[2];
    const float* b_enc  = (const float*)d_in[3];
    const float* W_pred = (const float*)d_in[4];
    const float* b_pred = (const float*)d_in[5];
    const float* W_out  = (const float*)d_in[6];
    const float* b_out  = (const float*)d_in[7];
    float* out = (float*)d_out;

    cudaFuncSetAttribute(joint_kernel,
                         cudaFuncAttributeMaxDynamicSharedMemorySize, JOINT_SMEM);

    // 1) frag-shuffle all inputs to fp16
    convert_kernel<<<(FRAG_TOTAL + 255) / 256, 256>>>(
        encoder_out, predictor_out, W_enc, W_pred, W_out);

    // 2) projections on tensor cores: 100 enc + 25 pred CTAs
    proj_mma_kernel<<<125, 256>>>(b_enc, b_pred);

    // 3) joint: 25 t-tiles x 7 u-tiles x 8 b = 1400 CTAs, 2/SM
    joint_kernel<<<1400, 256, JOINT_SMEM>>>(b_out, out);
}

// round 16
// speedup vs baseline: 1.2547x; 1.2547x over previous
#include <cuda_runtime.h>
#include <cuda_fp16.h>
#include <cstdint>

#define B_  8
#define T_  200
#define U_  50
#define DE  512
#define DP  640
#define DJ  640
#define V_  1024

#define MT     64                  // M rows per CTA (8 t x 8 u)
#define NTILE  256                 // vocab cols per CTA pass
#define NPASS  (V_ / NTILE)        // 4
#define KSTEPS (DJ / 16)           // 40 k16 steps

#define SA   648   // As stride halves; 324 words, %32=4 -> ldsm conflict-free
#define SAW  324

#define AS_BYTES   (MT * SA * 2)               // 82944
#define ENC_OFF    AS_BYTES
#define PRED_OFF   (ENC_OFF + 8 * 64 * 4)      // +2048
#define JOINT_SMEM (PRED_OFF + 8 * 64 * 4)     // 87040

// Scratch
__device__ float  g_enc [B_ * T_ * DJ];
__device__ float  g_pred[B_ * U_ * DJ];
// W pre-shuffled into mma B-fragment order:
// uint4 index = (n16 * KSTEPS + kstep) * 32 + lane
__device__ __align__(16) __half g_wh[V_ * DJ];

// ---------------------------------------------------------------------------
__device__ __forceinline__ uint32_t smem_u32(const void* p) {
    return (uint32_t)__cvta_generic_to_shared(p);
}
__device__ __forceinline__ void ldsm_x4(uint32_t& r0, uint32_t& r1, uint32_t& r2,
                                        uint32_t& r3, uint32_t a) {
    asm volatile("ldmatrix.sync.aligned.m8n8.x4.shared.b16 {%0,%1,%2,%3}, [%4];\n"
                 : "=r"(r0), "=r"(r1), "=r"(r2), "=r"(r3) : "r"(a));
}
__device__ __forceinline__ float tanh_fast(float x) {
    float y;
    asm("tanh.approx.f32 %0, %1;" : "=f"(y) : "f"(x));
    return y;
}
__device__ __forceinline__ uint32_t packh2(float a, float b) {
    half2 h = __floats2half2_rn(a, b);
    return *(uint32_t*)&h;
}

// ---------------------------------------------------------------------------
// Merged prep kernel:
//   z=0: enc projection (32x64 fp32 tiles)
//   z=1: pred projection
//   z=2: W_out fp32 -> fp16 frag-shuffle (first 320 (y*10+x) slots)
// ---------------------------------------------------------------------------
__global__ __launch_bounds__(256)
void prep_kernel(const float* __restrict__ Aenc, const float* __restrict__ Wenc,
                 const float* __restrict__ benc, float* __restrict__ Cenc,
                 const float* __restrict__ Apred, const float* __restrict__ Wpred,
                 const float* __restrict__ bpred, float* __restrict__ Cpred,
                 const float* __restrict__ Wout, uint4* __restrict__ Wh) {
    int z = blockIdx.z;
    int tid = threadIdx.x;

    if (z == 2) {
        int blk = blockIdx.y * gridDim.x + blockIdx.x;
        if (blk >= 320) return;
        int gid = blk * 256 + tid;              // 0..81919
        int lane = gid & 31;
        int rest = gid >> 5;
        int ks = rest % KSTEPS;
        int n16 = rest / KSTEPS;
        int g = lane >> 2, tg = lane & 3;
        const float* r0p = Wout + (size_t)(n16 * 16 + g) * DJ + ks * 16 + tg * 2;
        const float* r1p = r0p + 8 * DJ;
        float2 w0 = *(const float2*)(r0p);
        float2 w1 = *(const float2*)(r0p + 8);
        float2 w2 = *(const float2*)(r1p);
        float2 w3 = *(const float2*)(r1p + 8);
        uint4 o;
        o.x = packh2(w0.x, w0.y);
        o.y = packh2(w1.x, w1.y);
        o.z = packh2(w2.x, w2.y);
        o.w = packh2(w3.x, w3.y);
        Wh[gid] = o;
        return;
    }

    const float* A    = z ? Apred : Aenc;
    const float* W    = z ? Wpred : Wenc;
    const float* bias = z ? bpred : benc;
    float*       C    = z ? Cpred : Cenc;
    int M = z ? (B_ * U_) : (B_ * T_);
    int D = z ? DP : DE;

    int m0 = blockIdx.y * 32;
    if (m0 >= M) return;
    int j0 = blockIdx.x * 64;

    __shared__ float As[32][17];
    __shared__ float Ws[64][17];
    int tx = tid & 15, ty = tid >> 4;

    float acc[2][4];
    #pragma unroll
    for (int i = 0; i < 2; i++)
        #pragma unroll
        for (int j = 0; j < 4; j++) acc[i][j] = 0.f;

    for (int kt = 0; kt < D; kt += 16) {
        #pragma unroll
        for (int i = 0; i < 2; i++) {
            int idx = tid + i * 256;
            int r = idx >> 4, k = idx & 15;
            int m = m0 + r;
            As[r][k] = (m < M) ? A[(size_t)m * D + kt + k] : 0.f;
        }
        #pragma unroll
        for (int i = 0; i < 4; i++) {
            int idx = tid + i * 256;
            int r = idx >> 4, k = idx & 15;
            Ws[r][k] = W[(size_t)(j0 + r) * D + kt + k];
        }
        __syncthreads();
        #pragma unroll
        for (int kk = 0; kk < 16; kk++) {
            float a0 = As[ty][kk], a1 = As[ty + 16][kk];
            float w[4];
            #pragma unroll
            for (int j = 0; j < 4; j++) w[j] = Ws[tx + j * 16][kk];
            #pragma unroll
            for (int j = 0; j < 4; j++) {
                acc[0][j] += a0 * w[j];
                acc[1][j] += a1 * w[j];
            }
        }
        __syncthreads();
    }
    #pragma unroll
    for (int i = 0; i < 2; i++) {
        int m = m0 + ty + i * 16;
        if (m >= M) continue;
        #pragma unroll
        for (int j = 0; j < 4; j++) {
            int jj = j0 + tx + j * 16;
            C[(size_t)m * DJ + jj] = acc[i][j] + bias[jj];
        }
    }
}

// ---------------------------------------------------------------------------
// Joint kernel: CTA = 64 M-rows (8t x 8u) x V=1024 in 4 passes of N=256.
// 256 threads = 8 warps (2m x 4n), warp tile 32x64, 2 CTAs/SM.
// Phase 2: no barriers, B streamed from L2 in frag order, A via ldsm.
// Output stores use __stcs (streaming) to avoid evicting W from L2.
// ---------------------------------------------------------------------------
extern __shared__ __align__(128) char dynsmem[];

__global__ __launch_bounds__(256, 2)
void joint_kernel(const float* __restrict__ bout, float* __restrict__ out) {
    half*  As    = (half*)dynsmem;
    float* encs  = (float*)(dynsmem + ENC_OFF);    // 8 x 64
    float* preds = (float*)(dynsmem + PRED_OFF);   // 8 x 64

    int tid = threadIdx.x;
    int wid = tid >> 5, lane = tid & 31;
    int g = lane >> 2, tg = lane & 3;
    int warp_m = wid >> 2, warp_n = wid & 3;   // 2 x 4

    int bx = blockIdx.x;               // 1400 CTAs: 25 t-tiles x 7 u-tiles x 8 b
    int b = bx / 175, r = bx % 175;
    int tt = r % 25, ut = r / 25;
    int t0 = tt * 8, u0 = ut * 8;

    uint32_t as_u = smem_u32(As);

    // ---- Phase 1: A = tanh(enc + pred), fp16, once ----
    const float* encp  = g_enc  + ((size_t)b * T_ + t0) * DJ;
    const float* predp = g_pred + ((size_t)b * U_ + u0) * DJ;
    for (int kc = 0; kc < DJ; kc += 64) {
        {   // enc 8x64 + pred 8x64: 256 float2 each, one of each per thread
            int rw = tid >> 5, kp = tid & 31;
            *(float2*)(encs + rw * 64 + kp * 2) =
                *(const float2*)(encp + (size_t)rw * DJ + kc + kp * 2);
            int u = u0 + rw;
            float2 pv = make_float2(0.f, 0.f);
            if (u < U_) pv = *(const float2*)(predp + (size_t)rw * DJ + kc + kp * 2);
            *(float2*)(preds + rw * 64 + kp * 2) = pv;
        }
        __syncthreads();
        #pragma unroll
        for (int i = 0; i < 8; i++) {      // 64 rows x 32 half2
            int idx = tid + i * 256;
            int row = idx >> 5, kp = idx & 31;   // row = t-local*8 + u-local
            float2 e = *(const float2*)(encs + ((row >> 3) << 6) + kp * 2);
            float2 p = *(const float2*)(preds + ((row & 7) << 6) + kp * 2);
            half2 h = __floats2half2_rn(tanh_fast(e.x + p.x), tanh_fast(e.y + p.y));
            *(half2*)(As + row * SA + kc + kp * 2) = h;
        }
        __syncthreads();
    }

    // ---- Phase 2: 4 vocab passes x 40 k16-steps. No barriers. ----
    int j = lane >> 3;
    int a_row = warp_m * 32 + (lane & 7) + (j & 1) * 8;   // + mt*16
    int a_col = (j >> 1) * 4;

    const uint4* wsh = (const uint4*)g_wh;

    for (int np = 0; np < NPASS; np++) {
        float acc[2][8][4];
        #pragma unroll
        for (int mt = 0; mt < 2; mt++)
            #pragma unroll
            for (int nt = 0; nt < 8; nt++)
                #pragma unroll
                for (int c = 0; c < 4; c++) acc[mt][nt][c] = 0.f;

        int n16b = np * (NTILE / 16) + warp_n * 4;
        const uint4* wp0 = wsh + ((size_t)(n16b + 0) * KSTEPS) * 32 + lane;
        const uint4* wp1 = wsh + ((size_t)(n16b + 1) * KSTEPS) * 32 + lane;
        const uint4* wp2 = wsh + ((size_t)(n16b + 2) * KSTEPS) * 32 + lane;
        const uint4* wp3 = wsh + ((size_t)(n16b + 3) * KSTEPS) * 32 + lane;

        for (int ks = 0; ks < KSTEPS; ks++) {
            uint4 bq[4];
            bq[0] = wp0[ks * 32];
            bq[1] = wp1[ks * 32];
            bq[2] = wp2[ks * 32];
            bq[3] = wp3[ks * 32];

            uint32_t a[2][4];
            #pragma unroll
            for (int mt = 0; mt < 2; mt++)
                ldsm_x4(a[mt][0], a[mt][1], a[mt][2], a[mt][3],
                        as_u + (uint32_t)((a_row + mt * 16) * SAW
                                          + ks * 8 + a_col) * 4);
            #pragma unroll
            for (int mt = 0; mt < 2; mt++) {
                #pragma unroll
                for (int nt = 0; nt < 8; nt++) {
                    uint32_t bf0 = (nt & 1) ? bq[nt >> 1].z : bq[nt >> 1].x;
                    uint32_t bf1 = (nt & 1) ? bq[nt >> 1].w : bq[nt >> 1].y;
                    asm volatile(
                        "mma.sync.aligned.m16n8k16.row.col.f32.f16.f16.f32 "
                        "{%0,%1,%2,%3}, {%4,%5,%6,%7}, {%8,%9}, {%0,%1,%2,%3};\n"
                        : "+f"(acc[mt][nt][0]), "+f"(acc[mt][nt][1]),
                          "+f"(acc[mt][nt][2]), "+f"(acc[mt][nt][3])
                        : "r"(a[mt][0]), "r"(a[mt][1]), "r"(a[mt][2]), "r"(a[mt][3]),
                          "r"(bf0), "r"(bf1));
                }
            }
        }

        // epilogue for this pass (streaming stores: keep W resident in L2)
        int n0 = np * NTILE;
        #pragma unroll
        for (int nt = 0; nt < 8; nt++) {
            int n = n0 + warp_n * 64 + nt * 8 + tg * 2;
            float bo0 = __ldg(bout + n);
            float bo1 = __ldg(bout + n + 1);
            #pragma unroll
            for (int mt = 0; mt < 2; mt++) {
                #pragma unroll
                for (int h = 0; h < 2; h++) {
                    int row = warp_m * 32 + mt * 16 + g + h * 8;
                    int t = t0 + (row >> 3), u = u0 + (row & 7);
                    if (u < U_) {
                        size_t base = ((((size_t)b * T_ + t) * U_ + u) * V_) + n;
                        float2 v = make_float2(acc[mt][nt][h * 2] + bo0,
                                               acc[mt][nt][h * 2 + 1] + bo1);
                        __stcs((float2*)(out + base), v);
                    }
                }
            }
        }
    }
}

// ---------------------------------------------------------------------------
extern "C" void kernel_launch(void* const* d_in, const int* in_sizes, int n_in,
                              void* d_out, int out_size) {
    const float* encoder_out   = (const float*)d_in[0];
    const float* predictor_out = (const float*)d_in[1];
    const float* W_enc  = (const float*)d_in[2];
    const float* b_enc  = (const float*)d_in[3];
    const float* W_pred = (const float*)d_in[4];
    const float* b_pred = (const float*)d_in[5];
    const float* W_out  = (const float*)d_in[6];
    const float* b_out  = (const float*)d_in[7];
    float* out = (float*)d_out;

    float* enc_buf;
    float* pred_buf;
    uint4* wh_buf;
    cudaGetSymbolAddress((void**)&enc_buf,  g_enc);
    cudaGetSymbolAddress((void**)&pred_buf, g_pred);
    cudaGetSymbolAddress((void**)&wh_buf,   g_wh);

    cudaFuncSetAttribute(joint_kernel,
                         cudaFuncAttributeMaxDynamicSharedMemorySize, JOINT_SMEM);

    {   // merged prep: z=0 enc proj, z=1 pred proj, z=2 W convert
        dim3 grid(DJ / 64, (B_ * T_ + 31) / 32, 3);
        prep_kernel<<<grid, 256>>>(encoder_out, W_enc, b_enc, enc_buf,
                                   predictor_out, W_pred, b_pred, pred_buf,
                                   W_out, wh_buf);
    }

    // joint: 25 t-tiles x 7 u-tiles x 8 b = 1400 CTAs, 2/SM
    joint_kernel<<<1400, 256, JOINT_SMEM>>>(b_out, out);
}

// round 17
// speedup vs baseline: 1.5522x; 1.2371x over previous
#include <cuda_runtime.h>
#include <cuda_fp16.h>
#include <cstdint>

#define B_  8
#define T_  200
#define U_  50
#define DE  512
#define DP  640
#define DJ  640
#define V_  1024

#define MT     64
#define NTILE  256
#define NPASS  (V_ / NTILE)        // 4
#define KSTEPS (DJ / 16)           // 40

#define SA   648
#define SAW  324

#define AS_BYTES   (MT * SA * 2)
#define ENC_OFF    AS_BYTES
#define PRED_OFF   (ENC_OFF + 8 * 64 * 4)
#define JOINT_SMEM (PRED_OFF + 8 * 64 * 4)     // 87040

// Projection frag buffer layout (uint4 units)
#define PENCF_OFF   0                          // 100 m16 x 32 ks x 32
#define PPREDF_OFF  102400                     // 25 m16 x 40 ks x 32
#define PWENCF_OFF  134400                     // 40 n16 x 32 ks x 32
#define PWPREDF_OFF 175360                     // 40 n16 x 40 ks x 32
#define PFRAG_TOTAL 226560
#define WOUT_FRAGS  81920                      // 64 n16 x 40 ks x 32 -> g_wh
#define CONV_TOTAL  (PFRAG_TOTAL + WOUT_FRAGS) // 308480

// Scratch
__device__ float g_enc [B_ * T_ * DJ];
__device__ float g_pred[B_ * U_ * DJ];
__device__ __align__(16) __half g_wh[V_ * DJ];       // joint W (frag order)
__device__ __align__(16) uint4  g_pfrag[PFRAG_TOTAL];// proj inputs (frag order)

// ---------------------------------------------------------------------------
__device__ __forceinline__ uint32_t smem_u32(const void* p) {
    return (uint32_t)__cvta_generic_to_shared(p);
}
__device__ __forceinline__ void ldsm_x4(uint32_t& r0, uint32_t& r1, uint32_t& r2,
                                        uint32_t& r3, uint32_t a) {
    asm volatile("ldmatrix.sync.aligned.m8n8.x4.shared.b16 {%0,%1,%2,%3}, [%4];\n"
                 : "=r"(r0), "=r"(r1), "=r"(r2), "=r"(r3) : "r"(a));
}
__device__ __forceinline__ float tanh_fast(float x) {
    float y;
    asm("tanh.approx.f32 %0, %1;" : "=f"(y) : "f"(x));
    return y;
}
__device__ __forceinline__ uint32_t packh2(float a, float b) {
    half2 h = __floats2half2_rn(a, b);
    return *(uint32_t*)&h;
}
#define MMA16816(acc, a0, a1, a2, a3, bf0, bf1)                               \
    asm volatile(                                                             \
        "mma.sync.aligned.m16n8k16.row.col.f32.f16.f16.f32 "                  \
        "{%0,%1,%2,%3}, {%4,%5,%6,%7}, {%8,%9}, {%0,%1,%2,%3};\n"             \
        : "+f"((acc)[0]), "+f"((acc)[1]), "+f"((acc)[2]), "+f"((acc)[3])      \
        : "r"(a0), "r"(a1), "r"(a2), "r"(a3), "r"(bf0), "r"(bf1))

// ---------------------------------------------------------------------------
// Flat convert: fp32 -> fp16 frag shuffles.
//   [0, PFRAG_TOTAL): proj inputs into g_pfrag
//   [PFRAG_TOTAL, CONV_TOTAL): W_out into g_wh (B-layout)
// A-layout frag: {x:[g][k], y:[g+8][k], z:[g][k+8], w:[g+8][k+8]}
// B-layout frag: {x:[g][k], y:[g][k+8], z:[g+8][k], w:[g+8][k+8]}
// ---------------------------------------------------------------------------
__global__ __launch_bounds__(256)
void convert_kernel(const float* __restrict__ enc, const float* __restrict__ pred,
                    const float* __restrict__ Wenc, const float* __restrict__ Wpred,
                    const float* __restrict__ Wout) {
    int gid = blockIdx.x * 256 + threadIdx.x;
    if (gid >= CONV_TOTAL) return;
    int lane = gid & 31;
    int g = lane >> 2, tg = lane & 3;

    const float* src;
    int r16, ks, D;
    bool aL;
    uint4* dst;
    if (gid < PPREDF_OFF) {
        int t = gid >> 5;                 src = enc;   D = DE;  aL = true;
        r16 = t / 32; ks = t % 32;        dst = g_pfrag + gid;
    } else if (gid < PWENCF_OFF) {
        int t = (gid - PPREDF_OFF) >> 5;  src = pred;  D = DP;  aL = true;
        r16 = t / 40; ks = t % 40;        dst = g_pfrag + gid;
    } else if (gid < PWPREDF_OFF) {
        int t = (gid - PWENCF_OFF) >> 5;  src = Wenc;  D = DE;  aL = false;
        r16 = t / 32; ks = t % 32;        dst = g_pfrag + gid;
    } else if (gid < PFRAG_TOTAL) {
        int t = (gid - PWPREDF_OFF) >> 5; src = Wpred; D = DP;  aL = false;
        r16 = t / 40; ks = t % 40;        dst = g_pfrag + gid;
    } else {
        int t = (gid - PFRAG_TOTAL) >> 5; src = Wout;  D = DJ;  aL = false;
        r16 = t / 40; ks = t % 40;        dst = (uint4*)g_wh + (gid - PFRAG_TOTAL);
    }

    const float* p00 = src + (size_t)(r16 * 16 + g) * D + ks * 16 + tg * 2;
    const float* p10 = p00 + 8 * D;
    float2 v00 = *(const float2*)p00;
    float2 v01 = *(const float2*)(p00 + 8);
    float2 v10 = *(const float2*)p10;
    float2 v11 = *(const float2*)(p10 + 8);
    uint4 o;
    o.x = packh2(v00.x, v00.y);
    o.w = packh2(v11.x, v11.y);
    if (aL) { o.y = packh2(v10.x, v10.y); o.z = packh2(v01.x, v01.y); }
    else    { o.y = packh2(v01.x, v01.y); o.z = packh2(v10.x, v10.y); }
    *dst = o;
}

// ---------------------------------------------------------------------------
// Projection GEMMs on tensor cores, properly gridded.
// 625 CTAs: bx<500 -> enc (m16 = bx/5, jc = bx%5), else pred.
// 8 warps/CTA, each warp = one n16 block (jc*8 + wid) over 128 cols/CTA.
// ---------------------------------------------------------------------------
__global__ __launch_bounds__(256)
void proj_mma_kernel(const float* __restrict__ benc, const float* __restrict__ bpred) {
    int bx = blockIdx.x;
    bool isP = bx >= 500;
    int lx = isP ? bx - 500 : bx;
    int m16 = lx / 5, jc = lx % 5;
    int KS = isP ? 40 : 32;
    const uint4* AF = g_pfrag + (isP ? PPREDF_OFF : PENCF_OFF);
    const uint4* BF = g_pfrag + (isP ? PWPREDF_OFF : PWENCF_OFF);
    const float* bias = isP ? bpred : benc;
    float* C = isP ? g_pred : g_enc;

    int wid = threadIdx.x >> 5, lane = threadIdx.x & 31;
    int g = lane >> 2, tg = lane & 3;
    int n16 = jc * 8 + wid;

    float acc[2][4];
    #pragma unroll
    for (int nb = 0; nb < 2; nb++)
        #pragma unroll
        for (int c = 0; c < 4; c++) acc[nb][c] = 0.f;

    const uint4* ap = AF + (size_t)m16 * KS * 32 + lane;
    const uint4* bp = BF + (size_t)n16 * KS * 32 + lane;

    #pragma unroll 4
    for (int ks = 0; ks < KS; ks++) {
        uint4 a  = ap[ks * 32];
        uint4 bq = bp[ks * 32];
        MMA16816(acc[0], a.x, a.y, a.z, a.w, bq.x, bq.y);
        MMA16816(acc[1], a.x, a.y, a.z, a.w, bq.z, bq.w);
    }

    int r0 = m16 * 16 + g;
    #pragma unroll
    for (int nb = 0; nb < 2; nb++) {
        int n = n16 * 16 + nb * 8 + tg * 2;
        float bo0 = bias[n], bo1 = bias[n + 1];
        *(float2*)(C + (size_t)r0 * DJ + n) =
            make_float2(acc[nb][0] + bo0, acc[nb][1] + bo1);
        *(float2*)(C + (size_t)(r0 + 8) * DJ + n) =
            make_float2(acc[nb][2] + bo0, acc[nb][3] + bo1);
    }
}

// ---------------------------------------------------------------------------
// Joint kernel — bit-identical to the 394.5us R16 version.
// ---------------------------------------------------------------------------
extern __shared__ __align__(128) char dynsmem[];

__global__ __launch_bounds__(256, 2)
void joint_kernel(const float* __restrict__ bout, float* __restrict__ out) {
    half*  As    = (half*)dynsmem;
    float* encs  = (float*)(dynsmem + ENC_OFF);
    float* preds = (float*)(dynsmem + PRED_OFF);

    int tid = threadIdx.x;
    int wid = tid >> 5, lane = tid & 31;
    int g = lane >> 2, tg = lane & 3;
    int warp_m = wid >> 2, warp_n = wid & 3;

    int bx = blockIdx.x;
    int b = bx / 175, r = bx % 175;
    int tt = r % 25, ut = r / 25;
    int t0 = tt * 8, u0 = ut * 8;

    uint32_t as_u = smem_u32(As);

    const float* encp  = g_enc  + ((size_t)b * T_ + t0) * DJ;
    const float* predp = g_pred + ((size_t)b * U_ + u0) * DJ;
    for (int kc = 0; kc < DJ; kc += 64) {
        {
            int rw = tid >> 5, kp = tid & 31;
            *(float2*)(encs + rw * 64 + kp * 2) =
                *(const float2*)(encp + (size_t)rw * DJ + kc + kp * 2);
            int u = u0 + rw;
            float2 pv = make_float2(0.f, 0.f);
            if (u < U_) pv = *(const float2*)(predp + (size_t)rw * DJ + kc + kp * 2);
            *(float2*)(preds + rw * 64 + kp * 2) = pv;
        }
        __syncthreads();
        #pragma unroll
        for (int i = 0; i < 8; i++) {
            int idx = tid + i * 256;
            int row = idx >> 5, kp = idx & 31;
            float2 e = *(const float2*)(encs + ((row >> 3) << 6) + kp * 2);
            float2 p = *(const float2*)(preds + ((row & 7) << 6) + kp * 2);
            half2 h = __floats2half2_rn(tanh_fast(e.x + p.x), tanh_fast(e.y + p.y));
            *(half2*)(As + row * SA + kc + kp * 2) = h;
        }
        __syncthreads();
    }

    int j = lane >> 3;
    int a_row = warp_m * 32 + (lane & 7) + (j & 1) * 8;
    int a_col = (j >> 1) * 4;

    const uint4* wsh = (const uint4*)g_wh;

    for (int np = 0; np < NPASS; np++) {
        float acc[2][8][4];
        #pragma unroll
        for (int mt = 0; mt < 2; mt++)
            #pragma unroll
            for (int nt = 0; nt < 8; nt++)
                #pragma unroll
                for (int c = 0; c < 4; c++) acc[mt][nt][c] = 0.f;

        int n16b = np * (NTILE / 16) + warp_n * 4;
        const uint4* wp0 = wsh + ((size_t)(n16b + 0) * KSTEPS) * 32 + lane;
        const uint4* wp1 = wsh + ((size_t)(n16b + 1) * KSTEPS) * 32 + lane;
        const uint4* wp2 = wsh + ((size_t)(n16b + 2) * KSTEPS) * 32 + lane;
        const uint4* wp3 = wsh + ((size_t)(n16b + 3) * KSTEPS) * 32 + lane;

        for (int ks = 0; ks < KSTEPS; ks++) {
            uint4 bq[4];
            bq[0] = wp0[ks * 32];
            bq[1] = wp1[ks * 32];
            bq[2] = wp2[ks * 32];
            bq[3] = wp3[ks * 32];

            uint32_t a[2][4];
            #pragma unroll
            for (int mt = 0; mt < 2; mt++)
                ldsm_x4(a[mt][0], a[mt][1], a[mt][2], a[mt][3],
                        as_u + (uint32_t)((a_row + mt * 16) * SAW
                                          + ks * 8 + a_col) * 4);
            #pragma unroll
            for (int mt = 0; mt < 2; mt++) {
                #pragma unroll
                for (int nt = 0; nt < 8; nt++) {
                    uint32_t bf0 = (nt & 1) ? bq[nt >> 1].z : bq[nt >> 1].x;
                    uint32_t bf1 = (nt & 1) ? bq[nt >> 1].w : bq[nt >> 1].y;
                    MMA16816(acc[mt][nt], a[mt][0], a[mt][1], a[mt][2], a[mt][3],
                             bf0, bf1);
                }
            }
        }

        int n0 = np * NTILE;
        #pragma unroll
        for (int nt = 0; nt < 8; nt++) {
            int n = n0 + warp_n * 64 + nt * 8 + tg * 2;
            float bo0 = __ldg(bout + n);
            float bo1 = __ldg(bout + n + 1);
            #pragma unroll
            for (int mt = 0; mt < 2; mt++) {
                #pragma unroll
                for (int h = 0; h < 2; h++) {
                    int row = warp_m * 32 + mt * 16 + g + h * 8;
                    int t = t0 + (row >> 3), u = u0 + (row & 7);
                    if (u < U_) {
                        size_t base = ((((size_t)b * T_ + t) * U_ + u) * V_) + n;
                        float2 v = make_float2(acc[mt][nt][h * 2] + bo0,
                                               acc[mt][nt][h * 2 + 1] + bo1);
                        __stcs((float2*)(out + base), v);
                    }
                }
            }
        }
    }
}

// ---------------------------------------------------------------------------
extern "C" void kernel_launch(void* const* d_in, const int* in_sizes, int n_in,
                              void* d_out, int out_size) {
    const float* encoder_out   = (const float*)d_in[0];
    const float* predictor_out = (const float*)d_in[1];
    const float* W_enc  = (const float*)d_in[2];
    const float* b_enc  = (const float*)d_in[3];
    const float* W_pred = (const float*)d_in[4];
    const float* b_pred = (const float*)d_in[5];
    const float* W_out  = (const float*)d_in[6];
    const float* b_out  = (const float*)d_in[7];
    float* out = (float*)d_out;

    cudaFuncSetAttribute(joint_kernel,
                         cudaFuncAttributeMaxDynamicSharedMemorySize, JOINT_SMEM);

    // 1) frag-shuffle all fp32 inputs to fp16 (proj frags + joint W)
    convert_kernel<<<(CONV_TOTAL + 255) / 256, 256>>>(
        encoder_out, predictor_out, W_enc, W_pred, W_out);

    // 2) projections on tensor cores: 500 enc + 125 pred CTAs
    proj_mma_kernel<<<625, 256>>>(b_enc, b_pred);

    // 3) joint: unchanged (1400 CTAs, 2/SM)
    joint_kernel<<<1400, 256, JOINT_SMEM>>>(b_out, out);
}